// round 14
// baseline (speedup 1.0000x reference)
#include <cuda_runtime.h>
#include <cuda_bf16.h>
#include <mma.h>
#include <math.h>

using namespace nvcuda;

#define B_  8
#define L_  128
#define H_  768
#define M_  (B_ * L_)      // 1024 rows
#define LL_ (L_ * L_)      // 16384 pairs per batch

// ---------------- scratch (no allocations allowed) ----------------
__device__ float g_Ap[4][M_ * H_];      // k-quarter partials of seq @ W1[:H]
__device__ float g_Cp[4][M_ * H_];      // k-quarter partials of seq @ W1[H:]
__device__ float g_lp[3][M_ * L_];      // h-slice partial span logits
__device__ float g_se[2 * M_];          // per-row start/end CE
__device__ float g_span_partial[256];   // per-bce-block BCE partials
__device__ unsigned int g_counter;      // last-block counter (self-resetting)
__device__ __nv_bfloat16 g_seqb[M_ * H_];        // bf16 copy of seq
__device__ __nv_bfloat16 g_W1b[2 * H_ * H_];     // bf16 copy of W1

// ---------------- f32x2 packed helpers ----------------
typedef unsigned long long ull;

__device__ __forceinline__ ull dup2(float v) {
    ull r; asm("mov.b64 %0, {%1, %2};" : "=l"(r) : "f"(v), "f"(v)); return r;
}
__device__ __forceinline__ ull pk2(float lo, float hi) {
    ull r; asm("mov.b64 %0, {%1, %2};" : "=l"(r) : "f"(lo), "f"(hi)); return r;
}
__device__ __forceinline__ void upk2(ull v, float& lo, float& hi) {
    asm("mov.b64 {%0, %1}, %2;" : "=f"(lo), "=f"(hi) : "l"(v));
}
__device__ __forceinline__ ull fma2_(ull a, ull b, ull c) {
    ull d; asm("fma.rn.f32x2 %0, %1, %2, %3;" : "=l"(d) : "l"(a), "l"(b), "l"(c)); return d;
}
__device__ __forceinline__ ull mul2_(ull a, ull b) {
    ull d; asm("mul.rn.f32x2 %0, %1, %2;" : "=l"(d) : "l"(a), "l"(b)); return d;
}
__device__ __forceinline__ ull add2_(ull a, ull b) {
    ull d; asm("add.rn.f32x2 %0, %1, %2;" : "=l"(d) : "l"(a), "l"(b)); return d;
}
__device__ __forceinline__ float rcp_(float x) {
    float r; asm("rcp.approx.f32 %0, %1;" : "=f"(r) : "f"(x)); return r;
}

// hoisted constants for gelu2 (A&S 7.1.27: 4 coeffs, u^-4, 1 rcp, no exp)
struct GK {
    ull irt2, one, half, nhalf, b1, b2, b3, b4;
};
__device__ __forceinline__ GK make_gk() {
    GK k;
    k.irt2  = dup2(0.70710678118654752f);
    k.one   = dup2(1.0f);
    k.half  = dup2(0.5f);
    k.nhalf = dup2(-0.5f);
    k.b1 = dup2(0.278393f);
    k.b2 = dup2(0.230389f);
    k.b3 = dup2(0.000972f);
    k.b4 = dup2(0.078108f);
    return k;
}

// packed GELU via A&S 7.1.27: erf(z) = 1 - (1+b1 z+b2 z^2+b3 z^3+b4 z^4)^-4.
// Sign-free: gelu(x) = 0.5x + 0.5|x| - 0.5|x| * u^-4.
__device__ __forceinline__ ull gelu2(ull x, const GK& k) {
    ull ax = x & 0x7FFFFFFF7FFFFFFFULL;
    ull z  = mul2_(ax, k.irt2);
    ull u  = fma2_(k.b4, z, k.b3);
    u = fma2_(u, z, k.b2);
    u = fma2_(u, z, k.b1);
    u = fma2_(u, z, k.one);
    ull u2 = mul2_(u, u);
    ull u4 = mul2_(u2, u2);
    float l, h; upk2(u4, l, h);
    ull r   = pk2(rcp_(l), rcp_(h));      // u^-4
    ull xh  = mul2_(x,  k.half);
    ull h2  = fma2_(ax, k.half, xh);      // 0.5x + 0.5|x|
    ull h1n = mul2_(ax, k.nhalf);         // -0.5|x|
    return fma2_(h1n, r, h2);
}

// ---------------- fp32 -> bf16 one-time convert (seq, W1) ---------------------
__global__ void __launch_bounds__(256) convert_kernel(
    const float* __restrict__ seq, const float* __restrict__ W1)
{
    if (blockIdx.x == 0 && threadIdx.x == 0) g_counter = 0u;
    int i4 = (blockIdx.x * 256 + threadIdx.x) << 2;
    if (i4 < M_ * H_) {
        float4 v = *(const float4*)(seq + i4);
        *(__nv_bfloat162*)(g_seqb + i4)     = __float22bfloat162_rn(make_float2(v.x, v.y));
        *(__nv_bfloat162*)(g_seqb + i4 + 2) = __float22bfloat162_rn(make_float2(v.z, v.w));
    } else {
        int j4 = i4 - M_ * H_;
        float4 v = *(const float4*)(W1 + j4);
        *(__nv_bfloat162*)(g_W1b + j4)     = __float22bfloat162_rn(make_float2(v.x, v.y));
        *(__nv_bfloat162*)(g_W1b + j4 + 2) = __float22bfloat162_rn(make_float2(v.z, v.w));
    }
}

// ---------------- bf16 wmma GEMM (k-split x4, vector bf16 loads/stores) ------
__global__ void __launch_bounds__(256) gemm_kernel()
{
    __shared__ __align__(16) __nv_bfloat16 As[128][40];  // 80B row (16B mult)
    __shared__ __align__(16) __nv_bfloat16 Bs[32][72];   // 144B row (16B mult)

    int tid = threadIdx.x;
    int wid = tid >> 5;
    int wm = wid >> 1;                 // 0..3
    int wn = wid & 1;                  // 0..1
    int m0 = blockIdx.y << 7;          // 8 m-tiles
    int n0 = blockIdx.x << 6;          // 24 n-tiles
    int kz = (int)blockIdx.z * 192;    // k-quarter offset
    int isC = (n0 >= H_);
    const __nv_bfloat16* Bbase = g_W1b + (isC ? (H_ * H_ + (n0 - H_)) : n0);

    wmma::fragment<wmma::accumulator, 16, 16, 16, float> acc[2][2];
#pragma unroll
    for (int i = 0; i < 2; i++)
#pragma unroll
        for (int j = 0; j < 2; j++) wmma::fill_fragment(acc[i][j], 0.0f);

    int a_row = tid >> 1;              // 0..127
    int a_c16 = (tid & 1) << 4;        // 0 or 16
    int b_k   = tid >> 3;              // 0..31
    int b_n8  = (tid & 7) << 3;        // 0..56

    const __nv_bfloat16* arow = g_seqb + (m0 + a_row) * H_ + kz + a_c16;
    const __nv_bfloat16* brow = Bbase + (kz + b_k) * H_ + b_n8;

    uint4 pa0 = *(const uint4*)(arow);
    uint4 pa1 = *(const uint4*)(arow + 8);
    uint4 pb  = *(const uint4*)(brow);

    for (int it = 0; it < 6; it++) {
        *(uint4*)(&As[a_row][a_c16 + 0]) = pa0;
        *(uint4*)(&As[a_row][a_c16 + 8]) = pa1;
        *(uint4*)(&Bs[b_k][b_n8]) = pb;
        __syncthreads();
        if (it < 5) {
            arow += 32;
            brow += 32 * H_;
            pa0 = *(const uint4*)(arow);
            pa1 = *(const uint4*)(arow + 8);
            pb  = *(const uint4*)(brow);
        }
#pragma unroll
        for (int sk = 0; sk < 2; sk++) {
            wmma::fragment<wmma::matrix_a, 16, 16, 16, __nv_bfloat16, wmma::row_major> af[2];
            wmma::fragment<wmma::matrix_b, 16, 16, 16, __nv_bfloat16, wmma::row_major> bf[2];
            wmma::load_matrix_sync(af[0], &As[(wm << 5) +  0][sk << 4], 40);
            wmma::load_matrix_sync(af[1], &As[(wm << 5) + 16][sk << 4], 40);
            wmma::load_matrix_sync(bf[0], &Bs[sk << 4][(wn << 5) +  0], 72);
            wmma::load_matrix_sync(bf[1], &Bs[sk << 4][(wn << 5) + 16], 72);
#pragma unroll
            for (int i = 0; i < 2; i++)
#pragma unroll
                for (int j = 0; j < 2; j++)
                    wmma::mma_sync(acc[i][j], af[i], bf[j], acc[i][j]);
        }
        __syncthreads();
    }

    float* dst = isC ? g_Cp[blockIdx.z] : g_Ap[blockIdx.z];
    int colbase = (isC ? (n0 - H_) : n0) + (wn << 5);
    int rowbase = m0 + (wm << 5);
#pragma unroll
    for (int i = 0; i < 2; i++)
#pragma unroll
        for (int j = 0; j < 2; j++)
            wmma::store_matrix_sync(dst + (rowbase + (i << 4)) * H_ + colbase + (j << 4),
                                    acc[i][j], H_, wmma::mem_row_major);
}

// ---------------- span partial logits: 32x32 tile x 1/3 of h ------------------
// grid (4,4,24): z = b*3 + slice. 256 thr = 4 h-quarters (64 h each) x 64.
// Each thread: 4(i) x 4(j) outputs = 8 packed gelu chains (2 i-pairs x 4 j).
__global__ void __launch_bounds__(256) span_kernel(
    const float* __restrict__ w2, const float* __restrict__ b1)
{
    __shared__ __align__(16) float sAt[4][16][34];  // [q][h-chunk][i] transposed
    __shared__ __align__(16) ull   sC2[4][32][19];  // [q][j][h-chunk] pre-dup'd
    __shared__ ull   sW2[4][16];
    __shared__ __align__(16) ull part[3][64][8];

    int tid = threadIdx.x;
    int q = tid >> 6;              // h-quarter 0..3
    int t = tid & 63;
    int ty = t >> 3;               // 0..7 -> 4 i-rows (2 pairs)
    int tx = t & 7;                // 0..7 -> 4 j-cols
    int zb = blockIdx.z;
    int b = zb / 3;
    int s = zb - b * 3;
    int i0 = blockIdx.y << 5;
    int j0 = blockIdx.x << 5;
    int hbase = s * 256 + q * 64;
    int baseA = (b * L_ + i0) * H_ + hbase;
    int baseC = (b * L_ + j0) * H_ + hbase;
    const float* wbase = w2 + hbase;
    const float* bbase = b1 + hbase;

    const GK gk = make_gk();

    int il = ty << 2, jl = tx << 2;
    ull acc[8];
#pragma unroll
    for (int k = 0; k < 8; k++) acc[k] = 0ULL;

    for (int hc = 0; hc < 64; hc += 16) {
        {
            int row = t >> 1;              // 0..31
            int c8  = (t & 1) << 3;        // 0 or 8
            int offA = baseA + row * H_ + hc + c8;
#pragma unroll
            for (int g = 0; g < 2; g++) {
                float4 a0 = *(const float4*)(g_Ap[0] + offA + (g << 2));
                float4 a1 = *(const float4*)(g_Ap[1] + offA + (g << 2));
                float4 a2 = *(const float4*)(g_Ap[2] + offA + (g << 2));
                float4 a3 = *(const float4*)(g_Ap[3] + offA + (g << 2));
                float4 vb = *(const float4*)(bbase + hc + c8 + (g << 2));
                int cc = c8 + (g << 2);
                sAt[q][cc + 0][row] = ((a0.x + a1.x) + (a2.x + a3.x)) + vb.x;
                sAt[q][cc + 1][row] = ((a0.y + a1.y) + (a2.y + a3.y)) + vb.y;
                sAt[q][cc + 2][row] = ((a0.z + a1.z) + (a2.z + a3.z)) + vb.z;
                sAt[q][cc + 3][row] = ((a0.w + a1.w) + (a2.w + a3.w)) + vb.w;
            }
            int offC = baseC + row * H_ + hc + c8;
#pragma unroll
            for (int g = 0; g < 2; g++) {
                float4 c0 = *(const float4*)(g_Cp[0] + offC + (g << 2));
                float4 c1 = *(const float4*)(g_Cp[1] + offC + (g << 2));
                float4 c2 = *(const float4*)(g_Cp[2] + offC + (g << 2));
                float4 c3 = *(const float4*)(g_Cp[3] + offC + (g << 2));
                int cc = c8 + (g << 2);
                sC2[q][row][cc + 0] = dup2((c0.x + c1.x) + (c2.x + c3.x));
                sC2[q][row][cc + 1] = dup2((c0.y + c1.y) + (c2.y + c3.y));
                sC2[q][row][cc + 2] = dup2((c0.z + c1.z) + (c2.z + c3.z));
                sC2[q][row][cc + 3] = dup2((c0.w + c1.w) + (c2.w + c3.w));
            }
        }
        if (t < 16) sW2[q][t] = dup2(wbase[hc + t]);
        __syncthreads();
#pragma unroll 2
        for (int h = 0; h < 16; h++) {
            ull aP0 = *(const ull*)(&sAt[q][h][il]);       // (i0,i1)
            ull aP1 = *(const ull*)(&sAt[q][h][il + 2]);   // (i2,i3)
            ull wd = sW2[q][h];
            ull c0 = sC2[q][jl + 0][h];
            ull c1 = sC2[q][jl + 1][h];
            ull c2 = sC2[q][jl + 2][h];
            ull c3 = sC2[q][jl + 3][h];
            acc[0] = fma2_(gelu2(add2_(aP0, c0), gk), wd, acc[0]);
            acc[1] = fma2_(gelu2(add2_(aP0, c1), gk), wd, acc[1]);
            acc[2] = fma2_(gelu2(add2_(aP0, c2), gk), wd, acc[2]);
            acc[3] = fma2_(gelu2(add2_(aP0, c3), gk), wd, acc[3]);
            acc[4] = fma2_(gelu2(add2_(aP1, c0), gk), wd, acc[4]);
            acc[5] = fma2_(gelu2(add2_(aP1, c1), gk), wd, acc[5]);
            acc[6] = fma2_(gelu2(add2_(aP1, c2), gk), wd, acc[6]);
            acc[7] = fma2_(gelu2(add2_(aP1, c3), gk), wd, acc[7]);
        }
        __syncthreads();
    }

    if (q) {
#pragma unroll
        for (int k = 0; k < 8; k++) part[q - 1][t][k] = acc[k];
    }
    __syncthreads();

    if (!q) {
#pragma unroll
        for (int k = 0; k < 8; k++)
            acc[k] = add2_(add2_(add2_(acc[k], part[0][t][k]), part[1][t][k]), part[2][t][k]);
        float lg[4][4];
#pragma unroll
        for (int k = 0; k < 4; k++) {
            upk2(acc[k],     lg[0][k], lg[1][k]);   // rows il, il+1
            upk2(acc[4 + k], lg[2][k], lg[3][k]);   // rows il+2, il+3
        }
        int i = i0 + il, j = j0 + jl;
        float* dst = g_lp[s] + (b * L_ + i) * L_ + j;
#pragma unroll
        for (int r = 0; r < 4; r++)
            *(float4*)(dst + r * L_) = make_float4(lg[r][0], lg[r][1], lg[r][2], lg[r][3]);
    }
}

// ---------------- BCE + fused start/end CE + final reduction ------------------
// 256 blocks x 256 thr. Warps 0..3 compute CE for rows blockIdx.x*4 + wid.
// Each thread then does BCE over 2 logits; last block does final reduce.
__global__ void __launch_bounds__(256) bce_kernel(
    const float* __restrict__ seq,
    const float* __restrict__ Ws, const float* __restrict__ bs,
    const float* __restrict__ We, const float* __restrict__ be,
    const int* __restrict__ spos, const int* __restrict__ epos,
    const int* __restrict__ spanp, const float* __restrict__ b2,
    float* __restrict__ out)
{
    __shared__ float red[256];
    __shared__ int isLast;
    int tid = threadIdx.x;
    int wid = tid >> 5, lane = tid & 31;

    // --- fused start/end CE (one token row per warp, warps 0..3) ---
    if (wid < 4) {
        int m = (blockIdx.x << 2) + wid;
        const float* row = seq + m * H_;
        float s0 = 0.f, s1 = 0.f, e0 = 0.f, e1 = 0.f;
        for (int h = lane; h < H_; h += 32) {
            float x = row[h];
            float2 ws = *(const float2*)(Ws + 2 * h);
            float2 we = *(const float2*)(We + 2 * h);
            s0 = fmaf(x, ws.x, s0);
            s1 = fmaf(x, ws.y, s1);
            e0 = fmaf(x, we.x, e0);
            e1 = fmaf(x, we.y, e1);
        }
#pragma unroll
        for (int o = 16; o; o >>= 1) {
            s0 += __shfl_down_sync(0xffffffffu, s0, o);
            s1 += __shfl_down_sync(0xffffffffu, s1, o);
            e0 += __shfl_down_sync(0xffffffffu, e0, o);
            e1 += __shfl_down_sync(0xffffffffu, e1, o);
        }
        if (lane == 0) {
            s0 += bs[0]; s1 += bs[1]; e0 += be[0]; e1 += be[1];
            float mx  = fmaxf(s0, s1);
            float lse = mx + logf(expf(s0 - mx) + expf(s1 - mx));
            g_se[m] = lse - (spos[m] ? s1 : s0);
            mx  = fmaxf(e0, e1);
            lse = mx + logf(expf(e0 - mx) + expf(e1 - mx));
            g_se[M_ + m] = lse - (epos[m] ? e1 : e0);
        }
    }
    __threadfence();   // make g_se writes visible device-wide before the atomic

    // --- span BCE over 2 logits per thread ---
    int idx = (blockIdx.x * 256 + tid) << 1;
    float b2v = b2[0];
    float2 p0 = *(const float2*)(g_lp[0] + idx);
    float2 p1 = *(const float2*)(g_lp[1] + idx);
    float2 p2 = *(const float2*)(g_lp[2] + idx);
    int2   zi = *(const int2*)(spanp + idx);

    float lg[2] = { (p0.x + p1.x) + p2.x + b2v, (p0.y + p1.y) + p2.y + b2v };
    int   zz[2] = { zi.x, zi.y };
    float bsum = 0.f;
#pragma unroll
    for (int u = 0; u < 2; u++) {
        float sg = lg[u];
        float z  = (float)zz[u];
        bsum += fmaxf(sg, 0.f) - sg * z + log1pf(__expf(-fabsf(sg)));
    }

    red[tid] = bsum;
    __syncthreads();
    for (int o = 128; o; o >>= 1) {
        if (tid < o) red[tid] += red[tid + o];
        __syncthreads();
    }
    if (tid == 0) {
        g_span_partial[blockIdx.x] = red[0];
        __threadfence();
        unsigned int old = atomicAdd(&g_counter, 1u);
        isLast = (old == 255u);
    }
    __syncthreads();

    if (isLast) {
        __threadfence();
        float se = 0.f;
        for (int v = tid; v < 2 * M_; v += 256) se += g_se[v];
        float sp = g_span_partial[tid];
        red[tid] = se * (1.0f / (float)M_) + sp * (1.0f / (float)(B_ * LL_));
        __syncthreads();
        for (int o = 128; o; o >>= 1) {
            if (tid < o) red[tid] += red[tid + o];
            __syncthreads();
        }
        if (tid == 0) { out[0] = red[0]; g_counter = 0u; }
    }
}

// ---------------- launch ----------------
extern "C" void kernel_launch(void* const* d_in, const int* in_sizes, int n_in,
                              void* d_out, int out_size)
{
    const float* seq   = (const float*)d_in[0];
    const int*   spos  = (const int*)  d_in[1];
    const int*   epos  = (const int*)  d_in[2];
    const int*   spanp = (const int*)  d_in[3];
    const float* Ws    = (const float*)d_in[4];
    const float* bs    = (const float*)d_in[5];
    const float* We    = (const float*)d_in[6];
    const float* be    = (const float*)d_in[7];
    const float* W1    = (const float*)d_in[8];
    const float* b1    = (const float*)d_in[9];
    const float* w2    = (const float*)d_in[10];
    const float* b2    = (const float*)d_in[11];
    float* out = (float*)d_out;

    convert_kernel<<<1920, 256>>>(seq, W1);
    gemm_kernel<<<dim3(24, 8, 4), 256>>>();
    span_kernel<<<dim3(4, 4, 24), 256>>>(w2, b1);
    bce_kernel<<<256, 256>>>(seq, Ws, bs, We, be, spos, epos, spanp, b2, out);
}

// round 15
// speedup vs baseline: 1.0713x; 1.0713x over previous
#include <cuda_runtime.h>
#include <cuda_bf16.h>
#include <mma.h>
#include <math.h>

using namespace nvcuda;

#define B_  8
#define L_  128
#define H_  768
#define M_  (B_ * L_)      // 1024 rows
#define LL_ (L_ * L_)      // 16384 pairs per batch

// ---------------- scratch (no allocations allowed) ----------------
__device__ float g_Ap[4][M_ * H_];      // k-quarter partials of seq @ W1[:H]
__device__ float g_Cp[4][M_ * H_];      // k-quarter partials of seq @ W1[H:]
__device__ float g_lp[3][M_ * L_];      // h-slice partial span logits
__device__ float g_se[2 * M_];          // per-row start/end CE
__device__ float g_span_partial[128];   // per-bce-block BCE partials
__device__ unsigned int g_counter;      // last-block counter (self-resetting)
__device__ __nv_bfloat16 g_seqb[M_ * H_];        // bf16 copy of seq
__device__ __nv_bfloat16 g_W1b[2 * H_ * H_];     // bf16 copy of W1

// ---------------- f32x2 packed helpers ----------------
typedef unsigned long long ull;

__device__ __forceinline__ ull dup2(float v) {
    ull r; asm("mov.b64 %0, {%1, %2};" : "=l"(r) : "f"(v), "f"(v)); return r;
}
__device__ __forceinline__ ull pk2(float lo, float hi) {
    ull r; asm("mov.b64 %0, {%1, %2};" : "=l"(r) : "f"(lo), "f"(hi)); return r;
}
__device__ __forceinline__ void upk2(ull v, float& lo, float& hi) {
    asm("mov.b64 {%0, %1}, %2;" : "=f"(lo), "=f"(hi) : "l"(v));
}
__device__ __forceinline__ ull fma2_(ull a, ull b, ull c) {
    ull d; asm("fma.rn.f32x2 %0, %1, %2, %3;" : "=l"(d) : "l"(a), "l"(b), "l"(c)); return d;
}
__device__ __forceinline__ ull mul2_(ull a, ull b) {
    ull d; asm("mul.rn.f32x2 %0, %1, %2;" : "=l"(d) : "l"(a), "l"(b)); return d;
}
__device__ __forceinline__ ull add2_(ull a, ull b) {
    ull d; asm("add.rn.f32x2 %0, %1, %2;" : "=l"(d) : "l"(a), "l"(b)); return d;
}
__device__ __forceinline__ float rcp_(float x) {
    float r; asm("rcp.approx.f32 %0, %1;" : "=f"(r) : "f"(x)); return r;
}

// hoisted constants for gelu2 (A&S 7.1.27: 4 coeffs, u^-4, 1 rcp, no exp)
struct GK {
    ull irt2, one, half, nhalf, b1, b2, b3, b4;
};
__device__ __forceinline__ GK make_gk() {
    GK k;
    k.irt2  = dup2(0.70710678118654752f);
    k.one   = dup2(1.0f);
    k.half  = dup2(0.5f);
    k.nhalf = dup2(-0.5f);
    k.b1 = dup2(0.278393f);
    k.b2 = dup2(0.230389f);
    k.b3 = dup2(0.000972f);
    k.b4 = dup2(0.078108f);
    return k;
}

// packed GELU via A&S 7.1.27: erf(z) = 1 - (1+b1 z+b2 z^2+b3 z^3+b4 z^4)^-4.
// Sign-free: gelu(x) = 0.5x + 0.5|x| - 0.5|x| * u^-4.
__device__ __forceinline__ ull gelu2(ull x, const GK& k) {
    ull ax = x & 0x7FFFFFFF7FFFFFFFULL;
    ull z  = mul2_(ax, k.irt2);
    ull u  = fma2_(k.b4, z, k.b3);
    u = fma2_(u, z, k.b2);
    u = fma2_(u, z, k.b1);
    u = fma2_(u, z, k.one);
    ull u2 = mul2_(u, u);
    ull u4 = mul2_(u2, u2);
    float l, h; upk2(u4, l, h);
    ull r   = pk2(rcp_(l), rcp_(h));      // u^-4
    ull xh  = mul2_(x,  k.half);
    ull h2  = fma2_(ax, k.half, xh);      // 0.5x + 0.5|x|
    ull h1n = mul2_(ax, k.nhalf);         // -0.5|x|
    return fma2_(h1n, r, h2);
}

// ---------------- convert (fp32->bf16) + fused start/end CE -------------------
// blocks [0,1920): convert seq/W1. blocks [1920,2048): CE, one row per warp.
__global__ void __launch_bounds__(256) convert_kernel(
    const float* __restrict__ seq, const float* __restrict__ W1,
    const float* __restrict__ Ws, const float* __restrict__ bs,
    const float* __restrict__ We, const float* __restrict__ be,
    const int* __restrict__ spos, const int* __restrict__ epos)
{
    if (blockIdx.x == 0 && threadIdx.x == 0) g_counter = 0u;
    if (blockIdx.x < 1920) {
        int i4 = (blockIdx.x * 256 + threadIdx.x) << 2;
        if (i4 < M_ * H_) {
            float4 v = *(const float4*)(seq + i4);
            *(__nv_bfloat162*)(g_seqb + i4)     = __float22bfloat162_rn(make_float2(v.x, v.y));
            *(__nv_bfloat162*)(g_seqb + i4 + 2) = __float22bfloat162_rn(make_float2(v.z, v.w));
        } else {
            int j4 = i4 - M_ * H_;
            float4 v = *(const float4*)(W1 + j4);
            *(__nv_bfloat162*)(g_W1b + j4)     = __float22bfloat162_rn(make_float2(v.x, v.y));
            *(__nv_bfloat162*)(g_W1b + j4 + 2) = __float22bfloat162_rn(make_float2(v.z, v.w));
        }
    } else {
        int wid = threadIdx.x >> 5, lane = threadIdx.x & 31;
        int m = ((blockIdx.x - 1920) << 3) + wid;
        const float* row = seq + m * H_;
        float s0 = 0.f, s1 = 0.f, e0 = 0.f, e1 = 0.f;
        for (int h = lane; h < H_; h += 32) {
            float x = row[h];
            float2 ws = *(const float2*)(Ws + 2 * h);
            float2 we = *(const float2*)(We + 2 * h);
            s0 = fmaf(x, ws.x, s0);
            s1 = fmaf(x, ws.y, s1);
            e0 = fmaf(x, we.x, e0);
            e1 = fmaf(x, we.y, e1);
        }
#pragma unroll
        for (int o = 16; o; o >>= 1) {
            s0 += __shfl_down_sync(0xffffffffu, s0, o);
            s1 += __shfl_down_sync(0xffffffffu, s1, o);
            e0 += __shfl_down_sync(0xffffffffu, e0, o);
            e1 += __shfl_down_sync(0xffffffffu, e1, o);
        }
        if (lane == 0) {
            s0 += bs[0]; s1 += bs[1]; e0 += be[0]; e1 += be[1];
            float mx  = fmaxf(s0, s1);
            float lse = mx + logf(expf(s0 - mx) + expf(s1 - mx));
            g_se[m] = lse - (spos[m] ? s1 : s0);
            mx  = fmaxf(e0, e1);
            lse = mx + logf(expf(e0 - mx) + expf(e1 - mx));
            g_se[M_ + m] = lse - (epos[m] ? e1 : e0);
        }
    }
}

// ---------------- bf16 wmma GEMM (k-split x4, vector bf16 loads/stores) ------
__global__ void __launch_bounds__(256) gemm_kernel()
{
    __shared__ __align__(16) __nv_bfloat16 As[128][40];  // 80B row (16B mult)
    __shared__ __align__(16) __nv_bfloat16 Bs[32][72];   // 144B row (16B mult)

    int tid = threadIdx.x;
    int wid = tid >> 5;
    int wm = wid >> 1;                 // 0..3
    int wn = wid & 1;                  // 0..1
    int m0 = blockIdx.y << 7;          // 8 m-tiles
    int n0 = blockIdx.x << 6;          // 24 n-tiles
    int kz = (int)blockIdx.z * 192;    // k-quarter offset
    int isC = (n0 >= H_);
    const __nv_bfloat16* Bbase = g_W1b + (isC ? (H_ * H_ + (n0 - H_)) : n0);

    wmma::fragment<wmma::accumulator, 16, 16, 16, float> acc[2][2];
#pragma unroll
    for (int i = 0; i < 2; i++)
#pragma unroll
        for (int j = 0; j < 2; j++) wmma::fill_fragment(acc[i][j], 0.0f);

    int a_row = tid >> 1;              // 0..127
    int a_c16 = (tid & 1) << 4;        // 0 or 16
    int b_k   = tid >> 3;              // 0..31
    int b_n8  = (tid & 7) << 3;        // 0..56

    const __nv_bfloat16* arow = g_seqb + (m0 + a_row) * H_ + kz + a_c16;
    const __nv_bfloat16* brow = Bbase + (kz + b_k) * H_ + b_n8;

    uint4 pa0 = *(const uint4*)(arow);
    uint4 pa1 = *(const uint4*)(arow + 8);
    uint4 pb  = *(const uint4*)(brow);

    for (int it = 0; it < 6; it++) {
        *(uint4*)(&As[a_row][a_c16 + 0]) = pa0;
        *(uint4*)(&As[a_row][a_c16 + 8]) = pa1;
        *(uint4*)(&Bs[b_k][b_n8]) = pb;
        __syncthreads();
        if (it < 5) {
            arow += 32;
            brow += 32 * H_;
            pa0 = *(const uint4*)(arow);
            pa1 = *(const uint4*)(arow + 8);
            pb  = *(const uint4*)(brow);
        }
#pragma unroll
        for (int sk = 0; sk < 2; sk++) {
            wmma::fragment<wmma::matrix_a, 16, 16, 16, __nv_bfloat16, wmma::row_major> af[2];
            wmma::fragment<wmma::matrix_b, 16, 16, 16, __nv_bfloat16, wmma::row_major> bf[2];
            wmma::load_matrix_sync(af[0], &As[(wm << 5) +  0][sk << 4], 40);
            wmma::load_matrix_sync(af[1], &As[(wm << 5) + 16][sk << 4], 40);
            wmma::load_matrix_sync(bf[0], &Bs[sk << 4][(wn << 5) +  0], 72);
            wmma::load_matrix_sync(bf[1], &Bs[sk << 4][(wn << 5) + 16], 72);
#pragma unroll
            for (int i = 0; i < 2; i++)
#pragma unroll
                for (int j = 0; j < 2; j++)
                    wmma::mma_sync(acc[i][j], af[i], bf[j], acc[i][j]);
        }
        __syncthreads();
    }

    float* dst = isC ? g_Cp[blockIdx.z] : g_Ap[blockIdx.z];
    int colbase = (isC ? (n0 - H_) : n0) + (wn << 5);
    int rowbase = m0 + (wm << 5);
#pragma unroll
    for (int i = 0; i < 2; i++)
#pragma unroll
        for (int j = 0; j < 2; j++)
            wmma::store_matrix_sync(dst + (rowbase + (i << 4)) * H_ + colbase + (j << 4),
                                    acc[i][j], H_, wmma::mem_row_major);
}

// ---------------- span partial logits: 32x32 tile x 1/3 of h ------------------
// grid (4,4,24): z = b*3 + slice. 512 thr = 4 h-quarters (64 h each) x 128.
// Stages A = sum of 4 k-partials + b1, C = sum of 4 k-partials (combine fused).
__global__ void __launch_bounds__(512) span_kernel(
    const float* __restrict__ w2, const float* __restrict__ b1)
{
    __shared__ __align__(16) float sAt[4][16][34];  // [q][h-chunk][i] transposed
    __shared__ __align__(16) ull   sC2[4][32][19];  // [q][j][h-chunk] pre-dup'd
    __shared__ ull   sW2[4][16];
    __shared__ __align__(16) ull part[3][128][4];

    int tid = threadIdx.x;
    int q = tid >> 7;
    int t = tid & 127;
    int ty = t >> 3;
    int tx = t & 7;
    int zb = blockIdx.z;
    int b = zb / 3;
    int s = zb - b * 3;
    int i0 = blockIdx.y << 5;
    int j0 = blockIdx.x << 5;
    int hbase = s * 256 + q * 64;
    int baseA = (b * L_ + i0) * H_ + hbase;
    int baseC = (b * L_ + j0) * H_ + hbase;
    const float* wbase = w2 + hbase;
    const float* bbase = b1 + hbase;

    const GK gk = make_gk();

    int il = ty << 1, jl = tx << 2;
    ull acc0 = 0ULL, acc1 = 0ULL, acc2 = 0ULL, acc3 = 0ULL;

    for (int hc = 0; hc < 64; hc += 16) {
        {
            int row = t >> 2;              // 0..31
            int c4  = (t & 3) << 2;        // 0,4,8,12
            int offA = baseA + row * H_ + hc + c4;
            float4 a0 = *(const float4*)(g_Ap[0] + offA);
            float4 a1 = *(const float4*)(g_Ap[1] + offA);
            float4 a2 = *(const float4*)(g_Ap[2] + offA);
            float4 a3 = *(const float4*)(g_Ap[3] + offA);
            float4 vb = *(const float4*)(bbase + hc + c4);
            sAt[q][c4 + 0][row] = ((a0.x + a1.x) + (a2.x + a3.x)) + vb.x;
            sAt[q][c4 + 1][row] = ((a0.y + a1.y) + (a2.y + a3.y)) + vb.y;
            sAt[q][c4 + 2][row] = ((a0.z + a1.z) + (a2.z + a3.z)) + vb.z;
            sAt[q][c4 + 3][row] = ((a0.w + a1.w) + (a2.w + a3.w)) + vb.w;
            int offC = baseC + row * H_ + hc + c4;
            float4 c0 = *(const float4*)(g_Cp[0] + offC);
            float4 c1 = *(const float4*)(g_Cp[1] + offC);
            float4 c2 = *(const float4*)(g_Cp[2] + offC);
            float4 c3 = *(const float4*)(g_Cp[3] + offC);
            sC2[q][row][c4 + 0] = dup2((c0.x + c1.x) + (c2.x + c3.x));
            sC2[q][row][c4 + 1] = dup2((c0.y + c1.y) + (c2.y + c3.y));
            sC2[q][row][c4 + 2] = dup2((c0.z + c1.z) + (c2.z + c3.z));
            sC2[q][row][c4 + 3] = dup2((c0.w + c1.w) + (c2.w + c3.w));
        }
        if (t < 16) sW2[q][t] = dup2(wbase[hc + t]);
        __syncthreads();
#pragma unroll 4
        for (int h = 0; h < 16; h++) {
            ull aP = *(const ull*)(&sAt[q][h][il]);
            ull wd = sW2[q][h];
            ull c0 = sC2[q][jl + 0][h];
            ull c1 = sC2[q][jl + 1][h];
            ull c2 = sC2[q][jl + 2][h];
            ull c3 = sC2[q][jl + 3][h];
            acc0 = fma2_(gelu2(add2_(aP, c0), gk), wd, acc0);
            acc1 = fma2_(gelu2(add2_(aP, c1), gk), wd, acc1);
            acc2 = fma2_(gelu2(add2_(aP, c2), gk), wd, acc2);
            acc3 = fma2_(gelu2(add2_(aP, c3), gk), wd, acc3);
        }
        __syncthreads();
    }

    if (q) {
        part[q - 1][t][0] = acc0; part[q - 1][t][1] = acc1;
        part[q - 1][t][2] = acc2; part[q - 1][t][3] = acc3;
    }
    __syncthreads();

    if (!q) {
        acc0 = add2_(add2_(add2_(acc0, part[0][t][0]), part[1][t][0]), part[2][t][0]);
        acc1 = add2_(add2_(add2_(acc1, part[0][t][1]), part[1][t][1]), part[2][t][1]);
        acc2 = add2_(add2_(add2_(acc2, part[0][t][2]), part[1][t][2]), part[2][t][2]);
        acc3 = add2_(add2_(add2_(acc3, part[0][t][3]), part[1][t][3]), part[2][t][3]);
        float lg[2][4];
        upk2(acc0, lg[0][0], lg[1][0]);
        upk2(acc1, lg[0][1], lg[1][1]);
        upk2(acc2, lg[0][2], lg[1][2]);
        upk2(acc3, lg[0][3], lg[1][3]);
        int i = i0 + il, j = j0 + jl;
        float* dst = g_lp[s] + (b * L_ + i) * L_ + j;
        *(float4*)(dst)      = make_float4(lg[0][0], lg[0][1], lg[0][2], lg[0][3]);
        *(float4*)(dst + L_) = make_float4(lg[1][0], lg[1][1], lg[1][2], lg[1][3]);
    }
}

// ---------------- pure BCE + final reduction (CE already in g_se) -------------
__global__ void __launch_bounds__(256) bce_kernel(
    const int* __restrict__ spanp, const float* __restrict__ b2,
    float* __restrict__ out)
{
    __shared__ float red[256];
    __shared__ int isLast;
    int tid = threadIdx.x;
    int idx = (blockIdx.x * 256 + tid) << 2;   // 4 logits per thread
    float b2v = b2[0];

    float4 p0 = *(const float4*)(g_lp[0] + idx);
    float4 p1 = *(const float4*)(g_lp[1] + idx);
    float4 p2 = *(const float4*)(g_lp[2] + idx);
    int4   zi = *(const int4*)(spanp + idx);

    float lg[4] = { (p0.x + p1.x) + p2.x + b2v, (p0.y + p1.y) + p2.y + b2v,
                    (p0.z + p1.z) + p2.z + b2v, (p0.w + p1.w) + p2.w + b2v };
    int   zz[4] = { zi.x, zi.y, zi.z, zi.w };
    float bsum = 0.f;
#pragma unroll
    for (int u = 0; u < 4; u++) {
        float sg = lg[u];
        float z  = (float)zz[u];
        bsum += fmaxf(sg, 0.f) - sg * z + log1pf(__expf(-fabsf(sg)));
    }

    red[tid] = bsum;
    __syncthreads();
    for (int o = 128; o; o >>= 1) {
        if (tid < o) red[tid] += red[tid + o];
        __syncthreads();
    }
    if (tid == 0) {
        g_span_partial[blockIdx.x] = red[0];
        __threadfence();
        unsigned int old = atomicAdd(&g_counter, 1u);
        isLast = (old == 127u);
    }
    __syncthreads();

    if (isLast) {
        __threadfence();
        float se = 0.f;
        for (int v = tid; v < 2 * M_; v += 256) se += g_se[v];
        float sp = (tid < 128) ? g_span_partial[tid] : 0.f;
        red[tid] = se * (1.0f / (float)M_) + sp * (1.0f / (float)(B_ * LL_));
        __syncthreads();
        for (int o = 128; o; o >>= 1) {
            if (tid < o) red[tid] += red[tid + o];
            __syncthreads();
        }
        if (tid == 0) { out[0] = red[0]; g_counter = 0u; }
    }
}

// ---------------- launch ----------------
extern "C" void kernel_launch(void* const* d_in, const int* in_sizes, int n_in,
                              void* d_out, int out_size)
{
    const float* seq   = (const float*)d_in[0];
    const int*   spos  = (const int*)  d_in[1];
    const int*   epos  = (const int*)  d_in[2];
    const int*   spanp = (const int*)  d_in[3];
    const float* Ws    = (const float*)d_in[4];
    const float* bs    = (const float*)d_in[5];
    const float* We    = (const float*)d_in[6];
    const float* be    = (const float*)d_in[7];
    const float* W1    = (const float*)d_in[8];
    const float* b1    = (const float*)d_in[9];
    const float* w2    = (const float*)d_in[10];
    const float* b2    = (const float*)d_in[11];
    float* out = (float*)d_out;

    convert_kernel<<<2048, 256>>>(seq, W1, Ws, bs, We, be, spos, epos);
    gemm_kernel<<<dim3(24, 8, 4), 256>>>();
    span_kernel<<<dim3(4, 4, 24), 512>>>(w2, b1);
    bce_kernel<<<128, 256>>>(spanp, b2, out);
}